// round 15
// baseline (speedup 1.0000x reference)
#include <cuda_runtime.h>
#include <cstdint>

// Shapes: B=256, T=512, IN=128, H=256, W1=W2=512. M = B*T = 131072.
#define NRNN 256   // 8 Mg x 32 Ns, 128 threads, 2 CTAs/SM co-resident

// ---------------- static device scratch (no allocation allowed) ------------
__device__ float g_buf1[131072u * 512u];   // input-MLP act1; later attn weights
__device__ float g_buf2[131072u * 512u];   // input-MLP act2; later pool partials
__device__ float g_xin [512u * 65536u];    // xin_t  [T][B][H]
__device__ float g_hs  [512u * 65536u];    // hidden states [T][B][H]
__device__ float g_a1  [256 * 512];
__device__ float g_a2  [256 * 512];
__device__ unsigned g_flags[8 * 32 * 32];  // [mg][ns] flags, 128B stride (zero-init)

// ---------------------------------------------------------------------------
// helpers
// ---------------------------------------------------------------------------
__device__ __forceinline__ unsigned f2tf(float f)
{
    unsigned u;
    asm("cvt.rna.tf32.f32 %0, %1;" : "=r"(u) : "f"(f));
    return u;
}

// fast tanh: 1 - 2/(e^{2x}+1); exact limits at +-inf, MUFU-based.
__device__ __forceinline__ float ftanh(float x)
{
    float e = __expf(2.f * x);
    return 1.f - 2.f / (e + 1.f);
}

__device__ __forceinline__ void mma_tf32(
    float& c0, float& c1, float& c2, float& c3,
    unsigned a0, unsigned a1, unsigned a2, unsigned a3,
    unsigned b0, unsigned b1)
{
    asm volatile(
        "mma.sync.aligned.m16n8k8.row.col.f32.tf32.tf32.f32 "
        "{%0,%1,%2,%3},{%4,%5,%6,%7},{%8,%9},{%0,%1,%2,%3};"
        : "+f"(c0), "+f"(c1), "+f"(c2), "+f"(c3)
        : "r"(a0), "r"(a1), "r"(a2), "r"(a3), "r"(b0), "r"(b1));
}

// ---------------------------------------------------------------------------
// Big tf32 tensor-core GEMM (validated since R7): C = act(A@W + bias).
// Block 128x64, BK=32, 256 threads, register-prefetch double-buffered.
// ACT: 0 none, 1 relu, 2 exp(tanh()). PERM: 0 row-major; 1 (b*T+t)->[t][b][:].
// ---------------------------------------------------------------------------
template <int ACT, int PERM>
__global__ __launch_bounds__(256) void gemm_tc(
    const float* __restrict__ A, const float* __restrict__ W,
    const float* __restrict__ bias, float* __restrict__ C,
    int M, int N, int K)
{
    __shared__ unsigned As[128 * 36];
    __shared__ unsigned Bs[64 * 36];

    const int nb  = N >> 6;
    const int bm  = (int)(blockIdx.x / nb) << 7;
    const int bn  = (int)(blockIdx.x % nb) << 6;
    const int tid = threadIdx.x;
    const int w    = tid >> 5;
    const int lane = tid & 31;
    const int g    = lane >> 2;
    const int tg   = lane & 3;
    const int wm   = (w & 3) << 5;
    const int wn   = (w >> 2) << 5;

    const int arow = tid >> 3;
    const int akq  = (tid & 7) << 2;
    const int bk   = tid >> 4;
    const int bnq  = (tid & 15) << 2;

    float acc[2][4][4];
#pragma unroll
    for (int mi = 0; mi < 2; mi++)
#pragma unroll
        for (int ni = 0; ni < 4; ni++)
#pragma unroll
            for (int q = 0; q < 4; q++) acc[mi][ni][q] = 0.f;

    float4 pa[4], pb[2];
#pragma unroll
    for (int i = 0; i < 4; i++)
        pa[i] = *reinterpret_cast<const float4*>(
            A + (size_t)(bm + arow + (i << 5)) * K + akq);
#pragma unroll
    for (int i = 0; i < 2; i++)
        pb[i] = *reinterpret_cast<const float4*>(
            W + (size_t)(bk + (i << 4)) * N + bn + bnq);

    for (int p = 0; p < K; p += 32) {
#pragma unroll
        for (int i = 0; i < 4; i++) {
            uint4 q;
            q.x = f2tf(pa[i].x); q.y = f2tf(pa[i].y);
            q.z = f2tf(pa[i].z); q.w = f2tf(pa[i].w);
            *reinterpret_cast<uint4*>(&As[(arow + (i << 5)) * 36 + akq]) = q;
        }
#pragma unroll
        for (int i = 0; i < 2; i++) {
            int k = bk + (i << 4);
            Bs[(bnq + 0) * 36 + k] = f2tf(pb[i].x);
            Bs[(bnq + 1) * 36 + k] = f2tf(pb[i].y);
            Bs[(bnq + 2) * 36 + k] = f2tf(pb[i].z);
            Bs[(bnq + 3) * 36 + k] = f2tf(pb[i].w);
        }
        __syncthreads();

        if (p + 32 < K) {
#pragma unroll
            for (int i = 0; i < 4; i++)
                pa[i] = *reinterpret_cast<const float4*>(
                    A + (size_t)(bm + arow + (i << 5)) * K + p + 32 + akq);
#pragma unroll
            for (int i = 0; i < 2; i++)
                pb[i] = *reinterpret_cast<const float4*>(
                    W + (size_t)(p + 32 + bk + (i << 4)) * N + bn + bnq);
        }

#pragma unroll
        for (int ks = 0; ks < 4; ks++) {
            int kb = ks << 3;
            unsigned a[2][4];
#pragma unroll
            for (int mi = 0; mi < 2; mi++) {
                const unsigned* ap = &As[(wm + (mi << 4) + g) * 36 + tg + kb];
                a[mi][0] = ap[0];
                a[mi][1] = ap[8 * 36];
                a[mi][2] = ap[4];
                a[mi][3] = ap[8 * 36 + 4];
            }
#pragma unroll
            for (int ni = 0; ni < 4; ni++) {
                const unsigned* bp = &Bs[(wn + (ni << 3) + g) * 36 + tg + kb];
                unsigned b0 = bp[0], b1 = bp[4];
#pragma unroll
                for (int mi = 0; mi < 2; mi++)
                    mma_tf32(acc[mi][ni][0], acc[mi][ni][1],
                             acc[mi][ni][2], acc[mi][ni][3],
                             a[mi][0], a[mi][1], a[mi][2], a[mi][3], b0, b1);
            }
        }
        __syncthreads();
    }

#pragma unroll
    for (int mi = 0; mi < 2; mi++) {
#pragma unroll
        for (int ni = 0; ni < 4; ni++) {
            int col = bn + wn + (ni << 3) + (tg << 1);
            float b0v = __ldg(&bias[col]);
            float b1v = __ldg(&bias[col + 1]);
#pragma unroll
            for (int half = 0; half < 2; half++) {
                int r = bm + wm + (mi << 4) + g + (half << 3);
                float2 vv;
                vv.x = acc[mi][ni][half ? 2 : 0] + b0v;
                vv.y = acc[mi][ni][half ? 3 : 1] + b1v;
                if (ACT == 1) { vv.x = fmaxf(vv.x, 0.f); vv.y = fmaxf(vv.y, 0.f); }
                if (ACT == 2) { vv.x = __expf(ftanh(vv.x)); vv.y = __expf(ftanh(vv.y)); }
                if (PERM == 0) {
                    *reinterpret_cast<float2*>(&C[(size_t)r * N + col]) = vv;
                } else {
                    int b = r >> 9;
                    int t = r & 511;
                    *reinterpret_cast<float2*>(
                        &C[((size_t)t << 16) + (b << 8) + col]) = vv;
                }
            }
        }
    }
}

// ---------------------------------------------------------------------------
// Leaderless flag barrier: 32 CTAs per M-group, SINGLE-WARP polling (one flag
// per lane). Self-basing phases (zero-init globals; group members end equal).
// (R9: cluster barriers 2x slower. R13: all-thread polling 2x slower.)
// ---------------------------------------------------------------------------
__device__ __forceinline__ void mg_sync(int mg, int ns, unsigned phase)
{
    __syncthreads();
    if (threadIdx.x < 32) {
        if (threadIdx.x == 0) {
            unsigned* my = &g_flags[(mg * 32 + ns) * 32];
            asm volatile("st.release.gpu.u32 [%0], %1;" :: "l"(my), "r"(phase) : "memory");
        }
        const unsigned* peer = &g_flags[(mg * 32 + threadIdx.x) * 32];
        unsigned v;
        do {
            asm volatile("ld.acquire.gpu.u32 %0, [%1];" : "=r"(v) : "l"(peer) : "memory");
        } while (v < phase);
    }
    __syncthreads();
}

// ---------------------------------------------------------------------------
// Recurrent layers. 256 CTAs = 8 Mg(32 rows) x 32 Ns. 128 threads = 4 warps,
// 2 CTAs co-resident per SM (SMEM 101 KB/CTA). Weights tf32 W^T[n][k] in SMEM.
// Shared loader shape: 128 threads stage a 32x128 chunk (pf[8], ping-pong).
// Dual accumulator chains per warp (validated R11).
// ---------------------------------------------------------------------------
#define PADA 132
#define ABUF (32 * PADA)

// Layers 1/2: output 32x16; 4 warps = 2 row-tiles x 2 col-tiles. relu.
template <int KTOT>
__device__ __forceinline__ void layer12_mma(
    const float* __restrict__ A, int lda,
    const unsigned* __restrict__ Wt, int wstride,
    const float* __restrict__ bias_s,
    float* __restrict__ C, int ldc,
    unsigned* As, int bm, int bn)
{
    const int tid  = threadIdx.x;
    const int w    = tid >> 5;
    const int lane = tid & 31;
    const int g    = lane >> 2;
    const int tg   = lane & 3;
    constexpr int NC = KTOT / 128;

    const int r0 = (w & 1) << 4;
    const int n0 = (w >> 1) << 3;

    const int lr = tid >> 5;       // loader rows lr + 4i, i = 0..7
    const int lq = lane << 2;      // loader k-quad 0..124

    float4 pf[8];
#pragma unroll
    for (int i = 0; i < 8; i++)
        pf[i] = __ldcg(reinterpret_cast<const float4*>(
            A + (size_t)(bm + lr + i * 4) * lda + lq));

    float e0 = 0.f, e1 = 0.f, e2 = 0.f, e3 = 0.f;
    float o0 = 0.f, o1 = 0.f, o2 = 0.f, o3 = 0.f;

#pragma unroll
    for (int c = 0; c < NC; c++) {
        unsigned* buf = As + (c & 1) * ABUF;
#pragma unroll
        for (int i = 0; i < 8; i++) {
            uint4 q;
            q.x = f2tf(pf[i].x); q.y = f2tf(pf[i].y);
            q.z = f2tf(pf[i].z); q.w = f2tf(pf[i].w);
            *reinterpret_cast<uint4*>(buf + (lr + i * 4) * PADA + lq) = q;
        }
        __syncthreads();

        if (c + 1 < NC) {
            const float* An = A + (c + 1) * 128;
#pragma unroll
            for (int i = 0; i < 8; i++)
                pf[i] = __ldcg(reinterpret_cast<const float4*>(
                    An + (size_t)(bm + lr + i * 4) * lda + lq));
        }

        const unsigned* ap = buf + (r0 + g) * PADA + tg;
        const unsigned* bp = Wt + (size_t)(n0 + g) * wstride + c * 128 + tg;
#pragma unroll
        for (int k8 = 0; k8 < 16; k8 += 2) {
            int kb = k8 << 3;
            mma_tf32(e0, e1, e2, e3,
                     ap[kb], ap[8 * PADA + kb], ap[kb + 4], ap[8 * PADA + kb + 4],
                     bp[kb], bp[kb + 4]);
            int kc = kb + 8;
            mma_tf32(o0, o1, o2, o3,
                     ap[kc], ap[8 * PADA + kc], ap[kc + 4], ap[8 * PADA + kc + 4],
                     bp[kc], bp[kc + 4]);
        }
        // no trailing sync: next chunk writes the OTHER buffer.
    }

    int row0 = bm + r0 + g;
    int col  = bn + n0 + (tg << 1);
    float b0v = bias_s[n0 + (tg << 1)];
    float b1v = bias_s[n0 + (tg << 1) + 1];
    float2 v0, v1;
    v0.x = fmaxf(e0 + o0 + b0v, 0.f); v0.y = fmaxf(e1 + o1 + b1v, 0.f);
    v1.x = fmaxf(e2 + o2 + b0v, 0.f); v1.y = fmaxf(e3 + o3 + b1v, 0.f);
    __stcg(reinterpret_cast<float2*>(&C[(size_t)row0 * ldc + col]), v0);
    __stcg(reinterpret_cast<float2*>(&C[(size_t)(row0 + 8) * ldc + col]), v1);
    // mg_sync opens with __syncthreads.
}

// Layer 3: output 32x8, K=512. 4 warps = 2 row-tiles x 2 k8-halves (kh).
// Same shared staging as layers 1/2; kh partials merged via xchg; tanh(v+xin).
__device__ __forceinline__ void layer3_mma(
    const float* __restrict__ A,            // g_a2, lda = 512
    const unsigned* __restrict__ Wt,        // 8 cols, stride 516
    const float* __restrict__ bias_s,
    float* __restrict__ C,                  // g_hs[t], ldc = 256
    const float* __restrict__ xin,
    unsigned* As, float* xchg, int bm, int bn3)
{
    const int tid  = threadIdx.x;
    const int w    = tid >> 5;
    const int lane = tid & 31;
    const int g    = lane >> 2;
    const int tg   = lane & 3;
    const int w2   = w & 1;        // row-tile
    const int kh   = w >> 1;       // k8-half within each chunk
    const int r0   = w2 << 4;
    const int lr   = tid >> 5;
    const int lq   = lane << 2;

    float4 pf[8];
#pragma unroll
    for (int i = 0; i < 8; i++)
        pf[i] = __ldcg(reinterpret_cast<const float4*>(
            A + (size_t)(bm + lr + i * 4) * 512 + lq));

    float e0 = 0.f, e1 = 0.f, e2 = 0.f, e3 = 0.f;
    float o0 = 0.f, o1 = 0.f, o2 = 0.f, o3 = 0.f;

#pragma unroll
    for (int c = 0; c < 4; c++) {
        unsigned* buf = As + (c & 1) * ABUF;
#pragma unroll
        for (int i = 0; i < 8; i++) {
            uint4 q;
            q.x = f2tf(pf[i].x); q.y = f2tf(pf[i].y);
            q.z = f2tf(pf[i].z); q.w = f2tf(pf[i].w);
            *reinterpret_cast<uint4*>(buf + (lr + i * 4) * PADA + lq) = q;
        }
        __syncthreads();

        if (c + 1 < 4) {
            const float* An = A + (c + 1) * 128;
#pragma unroll
            for (int i = 0; i < 8; i++)
                pf[i] = __ldcg(reinterpret_cast<const float4*>(
                    An + (size_t)(bm + lr + i * 4) * 512 + lq));
        }

        const unsigned* ap = buf + (r0 + g) * PADA + tg;
        const unsigned* bp = Wt + (size_t)g * 516 + c * 128 + tg;
        const int kbase = kh << 3;             // this warp's 8 k8s of the chunk
#pragma unroll
        for (int j = 0; j < 8; j += 2) {
            int kb = (kbase + j) << 3;
            mma_tf32(e0, e1, e2, e3,
                     ap[kb], ap[8 * PADA + kb], ap[kb + 4], ap[8 * PADA + kb + 4],
                     bp[kb], bp[kb + 4]);
            int kc = kb + 8;
            mma_tf32(o0, o1, o2, o3,
                     ap[kc], ap[8 * PADA + kc], ap[kc + 4], ap[8 * PADA + kc + 4],
                     bp[kc], bp[kc + 4]);
        }
    }

    float c0 = e0 + o0, c1 = e1 + o1, c2 = e2 + o2, c3 = e3 + o3;
    float* xb = xchg + w2 * 128 + lane * 4;
    if (kh == 1) { xb[0] = c0; xb[1] = c1; xb[2] = c2; xb[3] = c3; }
    __syncthreads();
    if (kh == 0) {
        c0 += xb[0]; c1 += xb[1]; c2 += xb[2]; c3 += xb[3];
        int row0 = bm + r0 + g;
        int col  = bn3 + (tg << 1);
        float b0v = bias_s[(tg << 1)];
        float b1v = bias_s[(tg << 1) + 1];
        float2 x0 = *reinterpret_cast<const float2*>(&xin[(size_t)row0 * 256 + col]);
        float2 x1 = *reinterpret_cast<const float2*>(&xin[(size_t)(row0 + 8) * 256 + col]);
        float2 v0, v1;
        v0.x = ftanh(c0 + b0v + x0.x); v0.y = ftanh(c1 + b1v + x0.y);
        v1.x = ftanh(c2 + b0v + x1.x); v1.y = ftanh(c3 + b1v + x1.y);
        __stcg(reinterpret_cast<float2*>(&C[(size_t)row0 * 256 + col]), v0);
        __stcg(reinterpret_cast<float2*>(&C[(size_t)(row0 + 8) * 256 + col]), v1);
    }
    // mg_sync opens with __syncthreads.
}

// SMEM (4B words): Wt1 16x260 | Wt2 16x516 | Wt3 8x516 | bias 48 | As 2x32x132 | xchg 256
#define SMF_WT1  0
#define SMF_WT2  4160
#define SMF_WT3  (4160 + 8256)
#define SMF_B    (SMF_WT3 + 4128)
#define SMF_AS   (SMF_B + 48)
#define SMF_XCHG (SMF_AS + 2 * ABUF)
#define SMF_TOT  (SMF_XCHG + 256)

__global__ __launch_bounds__(128, 2) void rnn_kernel(
    const float* __restrict__ W1, const float* __restrict__ b1,
    const float* __restrict__ W2, const float* __restrict__ b2,
    const float* __restrict__ W3, const float* __restrict__ b3)
{
    extern __shared__ unsigned smu[];
    unsigned* Wt1 = smu + SMF_WT1;
    unsigned* Wt2 = smu + SMF_WT2;
    unsigned* Wt3 = smu + SMF_WT3;
    float*    bs  = reinterpret_cast<float*>(smu + SMF_B);
    unsigned* As  = smu + SMF_AS;
    float*   xchg = reinterpret_cast<float*>(smu + SMF_XCHG);
    __shared__ unsigned s_base;

    const int tid = threadIdx.x;
    const int mg  = blockIdx.x >> 5;      // 0..7
    const int ns  = blockIdx.x & 31;      // 0..31
    const int bm  = mg << 5;              // 32-row group
    const int bn  = ns << 4;              // 16-col slice (l1,l2)
    const int bn3 = ns << 3;              // 8-col slice (l3)

    // self-basing phase: read my own flag (group members end a launch equal)
    if (tid == 0) {
        unsigned v;
        asm volatile("ld.acquire.gpu.u32 %0, [%1];"
                     : "=r"(v) : "l"(&g_flags[(mg * 32 + ns) * 32]) : "memory");
        s_base = v;
    }

    // one-time tf32 weight slice load: W^T[n][k]
    for (int idx = tid; idx < 4096; idx += 128) {       // Wt1 [16][256] str 260
        int c = idx >> 8, k = idx & 255;
        Wt1[c * 260 + k] = f2tf(__ldg(&W1[k * 512 + bn + c]));
    }
    for (int idx = tid; idx < 8192; idx += 128) {       // Wt2 [16][512] str 516
        int c = idx >> 9, k = idx & 511;
        Wt2[c * 516 + k] = f2tf(__ldg(&W2[k * 512 + bn + c]));
    }
    for (int idx = tid; idx < 4096; idx += 128) {       // Wt3 [8][512] str 516
        int c = idx >> 9, k = idx & 511;
        Wt3[c * 516 + k] = f2tf(__ldg(&W3[k * 256 + bn3 + c]));
    }
    if (tid < 16)      bs[tid]      = __ldg(&b1[bn + tid]);
    else if (tid < 32) bs[tid]      = __ldg(&b2[bn + tid - 16]);
    else if (tid < 40) bs[tid]      = __ldg(&b3[bn3 + tid - 32]);
    __syncthreads();

    unsigned ph = s_base;

    // t = 0: h_{-1} = 0  =>  a1 = relu(b1)  (32 rows x 16 cols)
    {
        int r  = tid >> 2;                 // 0..31
        int cq = (tid & 3) << 2;           // 0,4,8,12
        float4 v;
        v.x = fmaxf(bs[cq], 0.f);     v.y = fmaxf(bs[cq + 1], 0.f);
        v.z = fmaxf(bs[cq + 2], 0.f); v.w = fmaxf(bs[cq + 3], 0.f);
        __stcg(reinterpret_cast<float4*>(&g_a1[(size_t)(bm + r) * 512 + bn + cq]), v);
    }
    ph++;
    mg_sync(mg, ns, ph);

    for (int t = 0; t < 512; t++) {
        if (t > 0) {
            layer12_mma<256>(g_hs + (size_t)(t - 1) * 65536, 256,
                             Wt1, 260, bs, g_a1, 512, As, bm, bn);
            ph++; mg_sync(mg, ns, ph);
        }
        layer12_mma<512>(g_a1, 512, Wt2, 516, bs + 16,
                         g_a2, 512, As, bm, bn);
        ph++; mg_sync(mg, ns, ph);
        layer3_mma(g_a2, Wt3, bs + 32,
                   g_hs + (size_t)t * 65536,
                   g_xin + (size_t)t * 65536, As, xchg, bm, bn3);
        ph++; mg_sync(mg, ns, ph);
    }
}

// ---------------------------------------------------------------------------
// Attention pool, 2-stage: partials over T/4 segments, then reduce + divide.
// ---------------------------------------------------------------------------
__global__ __launch_bounds__(256) void pool_partial_kernel(
    const float* __restrict__ aw, const float* __restrict__ hs,
    float* __restrict__ pn, float* __restrict__ pd)
{
    int seg = blockIdx.x >> 8;                     // 0..3
    int i   = (blockIdx.x & 255) * 256 + threadIdx.x;
    float num = 0.f, den = 0.f;
    int t0 = seg * 128;
#pragma unroll 4
    for (int t = t0; t < t0 + 128; t++) {
        float a = __ldg(&aw[(size_t)t * 65536 + i]);
        float h = __ldg(&hs[(size_t)t * 65536 + i]);
        num += a * h;
        den += a;
    }
    pn[seg * 65536 + i] = num;
    pd[seg * 65536 + i] = den;
}

__global__ __launch_bounds__(256) void pool_final_kernel(
    const float* __restrict__ pn, const float* __restrict__ pd,
    float* __restrict__ out)
{
    int i = blockIdx.x * 256 + threadIdx.x;
    float num = 0.f, den = 0.f;
#pragma unroll
    for (int s = 0; s < 4; s++) {
        num += pn[s * 65536 + i];
        den += pd[s * 65536 + i];
    }
    out[i] = num / den;
}

// ---------------------------------------------------------------------------
extern "C" void kernel_launch(void* const* d_in, const int* in_sizes, int n_in,
                              void* d_out, int out_size)
{
    const float* x    = (const float*)d_in[0];
    const float* h_w1 = (const float*)d_in[1];
    const float* h_b1 = (const float*)d_in[2];
    const float* h_w2 = (const float*)d_in[3];
    const float* h_b2 = (const float*)d_in[4];
    const float* h_w3 = (const float*)d_in[5];
    const float* h_b3 = (const float*)d_in[6];
    const float* i_w1 = (const float*)d_in[7];
    const float* i_b1 = (const float*)d_in[8];
    const float* i_w2 = (const float*)d_in[9];
    const float* i_b2 = (const float*)d_in[10];
    const float* i_w3 = (const float*)d_in[11];
    const float* i_b3 = (const float*)d_in[12];
    const float* att_w = (const float*)d_in[13];
    const float* att_b = (const float*)d_in[14];
    float* out = (float*)d_out;

    float *buf1, *buf2, *xin, *hs;
    cudaGetSymbolAddress((void**)&buf1, g_buf1);
    cudaGetSymbolAddress((void**)&buf2, g_buf2);
    cudaGetSymbolAddress((void**)&xin,  g_xin);
    cudaGetSymbolAddress((void**)&hs,   g_hs);

    const int M = 131072;
    const int smem_rnn = SMF_TOT * 4;   // ~101 KB -> 2 CTAs/SM
    cudaFuncSetAttribute(rnn_kernel,
                         cudaFuncAttributeMaxDynamicSharedMemorySize, smem_rnn);

    // Input MLP (tensor cores): x -> relu -> relu -> xin_t (scatter [T][B][H])
    gemm_tc<1, 0><<<(M / 128) * (512 / 64), 256>>>(x,    i_w1, i_b1, buf1, M, 512, 128);
    gemm_tc<1, 0><<<(M / 128) * (512 / 64), 256>>>(buf1, i_w2, i_b2, buf2, M, 512, 512);
    gemm_tc<0, 1><<<(M / 128) * (256 / 64), 256>>>(buf2, i_w3, i_b3, xin,  M, 256, 512);

    // Persistent recurrence: 256 CTAs (2/SM), 32-CTA flag barrier per M-group
    rnn_kernel<<<NRNN, 128, smem_rnn>>>(h_w1, h_b1, h_w2, h_b2, h_w3, h_b3);

    // Attention weights: exp(tanh(hs @ att_w + att_b)) -> buf1 (reused)
    gemm_tc<2, 0><<<(M / 128) * (256 / 64), 256>>>(hs, att_w, att_b, buf1, M, 256, 256);

    // Pool over T, 2-stage (partials in buf2 scratch)
    pool_partial_kernel<<<1024, 256>>>(buf1, hs, buf2, buf2 + 262144);
    pool_final_kernel<<<256, 256>>>(buf2, buf2 + 262144, out);
}

// round 16
// speedup vs baseline: 1.0770x; 1.0770x over previous
#include <cuda_runtime.h>
#include <cstdint>

// Shapes: B=256, T=512, IN=128, H=256, W1=W2=512. M = B*T = 131072.
#define NRNN 128

// ---------------- static device scratch (no allocation allowed) ------------
__device__ float g_buf1[131072u * 512u];   // input-MLP act1; later attn weights
__device__ float g_buf2[131072u * 512u];   // input-MLP act2; later pool partials
__device__ float g_xin [512u * 65536u];    // xin_t  [T][B][H]
__device__ float g_hs  [512u * 65536u];    // hidden states [T][B][H]
__device__ float g_a1  [256 * 512];
__device__ float g_a2  [256 * 512];
__device__ unsigned g_flags[8 * 16 * 32];  // [mg][cta] flags, 128B stride (zero-init)

// ---------------------------------------------------------------------------
// helpers
// ---------------------------------------------------------------------------
__device__ __forceinline__ unsigned f2tf(float f)
{
    unsigned u;
    asm("cvt.rna.tf32.f32 %0, %1;" : "=r"(u) : "f"(f));
    return u;
}

// fast tanh: 1 - 2/(e^{2x}+1); exact limits at +-inf, MUFU-based.
__device__ __forceinline__ float ftanh(float x)
{
    float e = __expf(2.f * x);
    return 1.f - 2.f / (e + 1.f);
}

__device__ __forceinline__ void mma_tf32(
    float& c0, float& c1, float& c2, float& c3,
    unsigned a0, unsigned a1, unsigned a2, unsigned a3,
    unsigned b0, unsigned b1)
{
    asm volatile(
        "mma.sync.aligned.m16n8k8.row.col.f32.tf32.tf32.f32 "
        "{%0,%1,%2,%3},{%4,%5,%6,%7},{%8,%9},{%0,%1,%2,%3};"
        : "+f"(c0), "+f"(c1), "+f"(c2), "+f"(c3)
        : "r"(a0), "r"(a1), "r"(a2), "r"(a3), "r"(b0), "r"(b1));
}

// ---------------------------------------------------------------------------
// Big tf32 tensor-core GEMM: C = act(A@W + bias). Block 128x64, BK=32,
// 256 threads = 8 warps. PING-PONG smem tiles (one sync per iteration; mma of
// tile p overlaps LDG/cvt/STS of tile p+32 — same transformation that won R10
// in the rnn). Dynamic smem 55.3 KB; 2 CTAs/SM via launch bounds.
// ACT: 0 none, 1 relu, 2 exp(tanh()). PERM: 0 row-major; 1 (b*T+t)->[t][b][:].
// ---------------------------------------------------------------------------
#define GEMM_SMEM ((2 * 128 * 36 + 2 * 64 * 36) * 4)

template <int ACT, int PERM>
__global__ __launch_bounds__(256, 2) void gemm_tc(
    const float* __restrict__ A, const float* __restrict__ W,
    const float* __restrict__ bias, float* __restrict__ C,
    int M, int N, int K)
{
    extern __shared__ unsigned gsm[];
    unsigned* AsB = gsm;                    // 2 x [128][36]
    unsigned* BsB = gsm + 2 * 128 * 36;     // 2 x [64][36]

    const int nb  = N >> 6;
    const int bm  = (int)(blockIdx.x / nb) << 7;
    const int bn  = (int)(blockIdx.x % nb) << 6;
    const int tid = threadIdx.x;
    const int w    = tid >> 5;
    const int lane = tid & 31;
    const int g    = lane >> 2;
    const int tg   = lane & 3;
    const int wm   = (w & 3) << 5;
    const int wn   = (w >> 2) << 5;

    const int arow = tid >> 3;
    const int akq  = (tid & 7) << 2;
    const int bk   = tid >> 4;
    const int bnq  = (tid & 15) << 2;

    float acc[2][4][4];
#pragma unroll
    for (int mi = 0; mi < 2; mi++)
#pragma unroll
        for (int ni = 0; ni < 4; ni++)
#pragma unroll
            for (int q = 0; q < 4; q++) acc[mi][ni][q] = 0.f;

    float4 pa[4], pb[2];
#pragma unroll
    for (int i = 0; i < 4; i++)
        pa[i] = *reinterpret_cast<const float4*>(
            A + (size_t)(bm + arow + (i << 5)) * K + akq);
#pragma unroll
    for (int i = 0; i < 2; i++)
        pb[i] = *reinterpret_cast<const float4*>(
            W + (size_t)(bk + (i << 4)) * N + bn + bnq);

    for (int p = 0; p < K; p += 32) {
        const int bsel = (p >> 5) & 1;
        unsigned* As = AsB + bsel * (128 * 36);
        unsigned* Bs = BsB + bsel * (64 * 36);

        // stage current tiles (tf32-convert at STS)
#pragma unroll
        for (int i = 0; i < 4; i++) {
            uint4 q;
            q.x = f2tf(pa[i].x); q.y = f2tf(pa[i].y);
            q.z = f2tf(pa[i].z); q.w = f2tf(pa[i].w);
            *reinterpret_cast<uint4*>(&As[(arow + (i << 5)) * 36 + akq]) = q;
        }
#pragma unroll
        for (int i = 0; i < 2; i++) {
            int k = bk + (i << 4);
            Bs[(bnq + 0) * 36 + k] = f2tf(pb[i].x);
            Bs[(bnq + 1) * 36 + k] = f2tf(pb[i].y);
            Bs[(bnq + 2) * 36 + k] = f2tf(pb[i].z);
            Bs[(bnq + 3) * 36 + k] = f2tf(pb[i].w);
        }
        __syncthreads();

        if (p + 32 < K) {
#pragma unroll
            for (int i = 0; i < 4; i++)
                pa[i] = *reinterpret_cast<const float4*>(
                    A + (size_t)(bm + arow + (i << 5)) * K + p + 32 + akq);
#pragma unroll
            for (int i = 0; i < 2; i++)
                pb[i] = *reinterpret_cast<const float4*>(
                    W + (size_t)(p + 32 + bk + (i << 4)) * N + bn + bnq);
        }

#pragma unroll
        for (int ks = 0; ks < 4; ks++) {
            int kb = ks << 3;
            unsigned a[2][4];
#pragma unroll
            for (int mi = 0; mi < 2; mi++) {
                const unsigned* ap = &As[(wm + (mi << 4) + g) * 36 + tg + kb];
                a[mi][0] = ap[0];
                a[mi][1] = ap[8 * 36];
                a[mi][2] = ap[4];
                a[mi][3] = ap[8 * 36 + 4];
            }
#pragma unroll
            for (int ni = 0; ni < 4; ni++) {
                const unsigned* bp = &Bs[(wn + (ni << 3) + g) * 36 + tg + kb];
                unsigned b0 = bp[0], b1 = bp[4];
#pragma unroll
                for (int mi = 0; mi < 2; mi++)
                    mma_tf32(acc[mi][ni][0], acc[mi][ni][1],
                             acc[mi][ni][2], acc[mi][ni][3],
                             a[mi][0], a[mi][1], a[mi][2], a[mi][3], b0, b1);
            }
        }
        // no trailing sync: next iteration stages the OTHER buffer; its
        // __syncthreads transitively orders this mma before buffer reuse.
    }

#pragma unroll
    for (int mi = 0; mi < 2; mi++) {
#pragma unroll
        for (int ni = 0; ni < 4; ni++) {
            int col = bn + wn + (ni << 3) + (tg << 1);
            float b0v = __ldg(&bias[col]);
            float b1v = __ldg(&bias[col + 1]);
#pragma unroll
            for (int half = 0; half < 2; half++) {
                int r = bm + wm + (mi << 4) + g + (half << 3);
                float2 vv;
                vv.x = acc[mi][ni][half ? 2 : 0] + b0v;
                vv.y = acc[mi][ni][half ? 3 : 1] + b1v;
                if (ACT == 1) { vv.x = fmaxf(vv.x, 0.f); vv.y = fmaxf(vv.y, 0.f); }
                if (ACT == 2) { vv.x = __expf(ftanh(vv.x)); vv.y = __expf(ftanh(vv.y)); }
                if (PERM == 0) {
                    *reinterpret_cast<float2*>(&C[(size_t)r * N + col]) = vv;
                } else {
                    int b = r >> 9;
                    int t = r & 511;
                    *reinterpret_cast<float2*>(
                        &C[((size_t)t << 16) + (b << 8) + col]) = vv;
                }
            }
        }
    }
}

// ---------------------------------------------------------------------------
// Leaderless flag barrier: 16 CTAs per M-group, single-warp polling only.
// Self-basing phases (zero-init globals; group members end a launch equal).
// (R9: cluster barriers 2x slower. R13: all-thread polling 2x slower.
//  R15: 2 CTAs/SM with 32-CTA groups slower. This config is the optimum.)
// ---------------------------------------------------------------------------
__device__ __forceinline__ void mg_sync(int mg, int ns, unsigned phase)
{
    __syncthreads();
    if (threadIdx.x < 16) {
        if (threadIdx.x == 0) {
            unsigned* my = &g_flags[(mg * 16 + ns) * 32];
            asm volatile("st.release.gpu.u32 [%0], %1;" :: "l"(my), "r"(phase) : "memory");
        }
        const unsigned* peer = &g_flags[(mg * 16 + threadIdx.x) * 32];
        unsigned v;
        do {
            asm volatile("ld.acquire.gpu.u32 %0, [%1];" : "=r"(v) : "l"(peer) : "memory");
        } while (v < phase);
    }
    __syncthreads();
}

// ---------------------------------------------------------------------------
// Recurrent layers. 128 CTAs = 8 Mg(32 rows) x 16 Ns. 256 threads = 8 warps.
// Weights resident in SMEM as tf32 W^T[n][k]; double-buffered As staging
// (one sync per chunk); two interleaved accumulator chains per warp.
// ---------------------------------------------------------------------------
#define PADA 132
#define ABUF (32 * PADA)

// Layers 1/2: NCOLS=32, 8 warps = 2 row-tiles x 4 col-tiles, relu epilogue.
template <int KTOT>
__device__ __forceinline__ void layer_mma(
    const float* __restrict__ A, int lda,
    const unsigned* __restrict__ Wt, int wstride,
    const float* __restrict__ bias_s,
    float* __restrict__ C, int ldc,
    unsigned* As, int bm, int bn)
{
    const int tid  = threadIdx.x;
    const int w    = tid >> 5;
    const int lane = tid & 31;
    const int g    = lane >> 2;
    const int tg   = lane & 3;
    constexpr int NC = KTOT / 128;

    const int r0 = (w & 1) << 4;
    const int n0 = (w >> 1) << 3;

    const int lr = w;             // loader: rows w, w+8, w+16, w+24
    const int lq = lane << 2;     // loader k-quad 0..124

    float4 pf[4];
#pragma unroll
    for (int i = 0; i < 4; i++)
        pf[i] = __ldcg(reinterpret_cast<const float4*>(
            A + (size_t)(bm + lr + i * 8) * lda + lq));

    float e0 = 0.f, e1 = 0.f, e2 = 0.f, e3 = 0.f;   // even-k8 chain
    float o0 = 0.f, o1 = 0.f, o2 = 0.f, o3 = 0.f;   // odd-k8 chain

#pragma unroll
    for (int c = 0; c < NC; c++) {
        unsigned* buf = As + (c & 1) * ABUF;
#pragma unroll
        for (int i = 0; i < 4; i++) {
            uint4 q;
            q.x = f2tf(pf[i].x); q.y = f2tf(pf[i].y);
            q.z = f2tf(pf[i].z); q.w = f2tf(pf[i].w);
            *reinterpret_cast<uint4*>(buf + (lr + i * 8) * PADA + lq) = q;
        }
        __syncthreads();

        if (c + 1 < NC) {
            const float* An = A + (c + 1) * 128;
#pragma unroll
            for (int i = 0; i < 4; i++)
                pf[i] = __ldcg(reinterpret_cast<const float4*>(
                    An + (size_t)(bm + lr + i * 8) * lda + lq));
        }

        const unsigned* ap = buf + (r0 + g) * PADA + tg;
        const unsigned* bp = Wt + (size_t)(n0 + g) * wstride + c * 128 + tg;
#pragma unroll
        for (int k8 = 0; k8 < 16; k8 += 2) {
            int kb = k8 << 3;
            mma_tf32(e0, e1, e2, e3,
                     ap[kb], ap[8 * PADA + kb], ap[kb + 4], ap[8 * PADA + kb + 4],
                     bp[kb], bp[kb + 4]);
            int kc = kb + 8;
            mma_tf32(o0, o1, o2, o3,
                     ap[kc], ap[8 * PADA + kc], ap[kc + 4], ap[8 * PADA + kc + 4],
                     bp[kc], bp[kc + 4]);
        }
        // no trailing sync: next chunk stores to the OTHER buffer.
    }

    int row0 = bm + r0 + g;
    int col  = bn + n0 + (tg << 1);
    float b0v = bias_s[n0 + (tg << 1)];
    float b1v = bias_s[n0 + (tg << 1) + 1];
    float2 v0, v1;
    v0.x = fmaxf(e0 + o0 + b0v, 0.f); v0.y = fmaxf(e1 + o1 + b1v, 0.f);
    v1.x = fmaxf(e2 + o2 + b0v, 0.f); v1.y = fmaxf(e3 + o3 + b1v, 0.f);
    __stcg(reinterpret_cast<float2*>(&C[(size_t)row0 * ldc + col]), v0);
    __stcg(reinterpret_cast<float2*>(&C[(size_t)(row0 + 8) * ldc + col]), v1);
    // mg_sync opens with __syncthreads.
}

// Layer 3: NCOLS=16, K=512. Parallel split-K: warp-group g2 = w>>2 owns
// K-chunks {2g2, 2g2+1}; per-group double-buffered As and named barrier (1+g2).
// Two interleaved accumulator chains. Partials merged via xchg; tanh(v+xin)
// epilogue by group 0.
__device__ __forceinline__ void layer3_mma(
    const float* __restrict__ A,            // g_a2, lda = 512
    const unsigned* __restrict__ Wt,        // stride 516
    const float* __restrict__ bias_s,
    float* __restrict__ C,                  // ldc = 256
    const float* __restrict__ xin,
    unsigned* As4, float* xchg, int bm, int bn)
{
    const int tid  = threadIdx.x;
    const int w    = tid >> 5;
    const int lane = tid & 31;
    const int g    = lane >> 2;
    const int tg   = lane & 3;
    const int g2   = w >> 2;               // k-half group 0/1
    const int w2   = w & 3;
    const int r0   = (w2 & 1) << 4;
    const int n0   = ((w2 >> 1) & 1) << 3;
    const int ltid = tid & 127;
    const int lr   = ltid >> 5;            // 0..3
    const int lq   = (ltid & 31) << 2;
    const int barid = 1 + g2;

    const float* A0 = A + (size_t)g2 * 256;   // k-offset of this group's chunks
    float4 pf[8];
#pragma unroll
    for (int i = 0; i < 8; i++)
        pf[i] = __ldcg(reinterpret_cast<const float4*>(
            A0 + (size_t)(bm + lr + i * 4) * 512 + lq));

    float e0 = 0.f, e1 = 0.f, e2 = 0.f, e3 = 0.f;
    float o0 = 0.f, o1 = 0.f, o2 = 0.f, o3 = 0.f;

#pragma unroll
    for (int cc = 0; cc < 2; cc++) {
        int c = (g2 << 1) + cc;
        unsigned* buf = As4 + ((g2 << 1) + cc) * ABUF;
#pragma unroll
        for (int i = 0; i < 8; i++) {
            uint4 q;
            q.x = f2tf(pf[i].x); q.y = f2tf(pf[i].y);
            q.z = f2tf(pf[i].z); q.w = f2tf(pf[i].w);
            *reinterpret_cast<uint4*>(buf + (lr + i * 4) * PADA + lq) = q;
        }
        asm volatile("bar.sync %0, 128;" :: "r"(barid));

        if (cc == 0) {
            const float* A1 = A0 + 128;
#pragma unroll
            for (int i = 0; i < 8; i++)
                pf[i] = __ldcg(reinterpret_cast<const float4*>(
                    A1 + (size_t)(bm + lr + i * 4) * 512 + lq));
        }

        const unsigned* ap = buf + (r0 + g) * PADA + tg;
        const unsigned* bp = Wt + (size_t)(n0 + g) * 516 + c * 128 + tg;
#pragma unroll
        for (int k8 = 0; k8 < 16; k8 += 2) {
            int kb = k8 << 3;
            mma_tf32(e0, e1, e2, e3,
                     ap[kb], ap[8 * PADA + kb], ap[kb + 4], ap[8 * PADA + kb + 4],
                     bp[kb], bp[kb + 4]);
            int kc = kb + 8;
            mma_tf32(o0, o1, o2, o3,
                     ap[kc], ap[8 * PADA + kc], ap[kc + 4], ap[8 * PADA + kc + 4],
                     bp[kc], bp[kc + 4]);
        }
        // distinct buffer per chunk: no trailing named barrier needed
    }

    float c0 = e0 + o0, c1 = e1 + o1, c2 = e2 + o2, c3 = e3 + o3;
    float* xb = xchg + w2 * 128 + lane * 4;
    if (g2 == 1) { xb[0] = c0; xb[1] = c1; xb[2] = c2; xb[3] = c3; }
    __syncthreads();
    if (g2 == 0) {
        c0 += xb[0]; c1 += xb[1]; c2 += xb[2]; c3 += xb[3];
        int row0 = bm + r0 + g;
        int col  = bn + n0 + (tg << 1);
        float b0v = bias_s[n0 + (tg << 1)];
        float b1v = bias_s[n0 + (tg << 1) + 1];
        float2 x0 = *reinterpret_cast<const float2*>(&xin[(size_t)row0 * 256 + col]);
        float2 x1 = *reinterpret_cast<const float2*>(&xin[(size_t)(row0 + 8) * 256 + col]);
        float2 v0, v1;
        v0.x = ftanh(c0 + b0v + x0.x); v0.y = ftanh(c1 + b1v + x0.y);
        v1.x = ftanh(c2 + b0v + x1.x); v1.y = ftanh(c3 + b1v + x1.y);
        __stcg(reinterpret_cast<float2*>(&C[(size_t)row0 * 256 + col]), v0);
        __stcg(reinterpret_cast<float2*>(&C[(size_t)(row0 + 8) * 256 + col]), v1);
    }
    // mg_sync opens with __syncthreads.
}

// SMEM (4B words): Wt1 32x260 | Wt2 32x516 | Wt3 16x516 | bias 80 | As 4x32x132 | xchg 512
#define SMF_WT1  0
#define SMF_WT2  8320
#define SMF_WT3  (8320 + 16512)
#define SMF_B    (SMF_WT3 + 8256)
#define SMF_AS   (SMF_B + 80)
#define SMF_XCHG (SMF_AS + 4 * ABUF)
#define SMF_TOT  (SMF_XCHG + 512)

__global__ __launch_bounds__(256, 1) void rnn_kernel(
    const float* __restrict__ W1, const float* __restrict__ b1,
    const float* __restrict__ W2, const float* __restrict__ b2,
    const float* __restrict__ W3, const float* __restrict__ b3)
{
    extern __shared__ unsigned smu[];
    unsigned* Wt1 = smu + SMF_WT1;
    unsigned* Wt2 = smu + SMF_WT2;
    unsigned* Wt3 = smu + SMF_WT3;
    float*    bs  = reinterpret_cast<float*>(smu + SMF_B);
    unsigned* As  = smu + SMF_AS;
    float*   xchg = reinterpret_cast<float*>(smu + SMF_XCHG);
    __shared__ unsigned s_base;

    const int tid = threadIdx.x;
    const int mg  = blockIdx.x >> 4;      // 0..7
    const int ns  = blockIdx.x & 15;      // 0..15
    const int bm  = mg << 5;              // 32-row group
    const int bn  = ns << 5;              // 32-col slice (l1,l2)
    const int bn3 = ns << 4;              // 16-col slice (l3)

    // self-basing phase: read my own flag (group members end a launch equal)
    if (tid == 0) {
        unsigned v;
        asm volatile("ld.acquire.gpu.u32 %0, [%1];"
                     : "=r"(v) : "l"(&g_flags[(mg * 16 + ns) * 32]) : "memory");
        s_base = v;
    }

    // one-time tf32 weight slice load: W^T[n][k]
    for (int idx = tid; idx < 8192; idx += 256) {       // Wt1 [32][256] str 260
        int c = idx >> 8, k = idx & 255;
        Wt1[c * 260 + k] = f2tf(__ldg(&W1[k * 512 + bn + c]));
    }
    for (int idx = tid; idx < 16384; idx += 256) {      // Wt2 [32][512] str 516
        int c = idx >> 9, k = idx & 511;
        Wt2[c * 516 + k] = f2tf(__ldg(&W2[k * 512 + bn + c]));
    }
    for (int idx = tid; idx < 8192; idx += 256) {       // Wt3 [16][512] str 516
        int c = idx >> 9, k = idx & 511;
        Wt3[c * 516 + k] = f2tf(__ldg(&W3[k * 256 + bn3 + c]));
    }
    if (tid < 32)      bs[tid]      = __ldg(&b1[bn + tid]);
    else if (tid < 64) bs[tid]      = __ldg(&b2[bn + tid - 32]);
    else if (tid < 80) bs[tid]      = __ldg(&b3[bn3 + tid - 64]);
    __syncthreads();

    unsigned ph = s_base;

    // t = 0: h_{-1} = 0  =>  a1 = relu(b1)
    {
        int r  = tid >> 3;
        int cb = (tid & 7) << 2;
        float4 v;
        v.x = fmaxf(bs[cb], 0.f);     v.y = fmaxf(bs[cb + 1], 0.f);
        v.z = fmaxf(bs[cb + 2], 0.f); v.w = fmaxf(bs[cb + 3], 0.f);
        __stcg(reinterpret_cast<float4*>(&g_a1[(size_t)(bm + r) * 512 + bn + cb]), v);
    }
    ph++;
    mg_sync(mg, ns, ph);

    for (int t = 0; t < 512; t++) {
        if (t > 0) {
            layer_mma<256>(g_hs + (size_t)(t - 1) * 65536, 256,
                           Wt1, 260, bs, g_a1, 512, As, bm, bn);
            ph++; mg_sync(mg, ns, ph);
        }
        layer_mma<512>(g_a1, 512, Wt2, 516, bs + 32,
                       g_a2, 512, As, bm, bn);
        ph++; mg_sync(mg, ns, ph);
        layer3_mma(g_a2, Wt3, bs + 64,
                   g_hs + (size_t)t * 65536,
                   g_xin + (size_t)t * 65536, As, xchg, bm, bn3);
        ph++; mg_sync(mg, ns, ph);
    }
}

// ---------------------------------------------------------------------------
// Attention pool, 2-stage: partials over T/4 segments, then reduce + divide.
// ---------------------------------------------------------------------------
__global__ __launch_bounds__(256) void pool_partial_kernel(
    const float* __restrict__ aw, const float* __restrict__ hs,
    float* __restrict__ pn, float* __restrict__ pd)
{
    int seg = blockIdx.x >> 8;                     // 0..3
    int i   = (blockIdx.x & 255) * 256 + threadIdx.x;
    float num = 0.f, den = 0.f;
    int t0 = seg * 128;
#pragma unroll 4
    for (int t = t0; t < t0 + 128; t++) {
        float a = __ldg(&aw[(size_t)t * 65536 + i]);
        float h = __ldg(&hs[(size_t)t * 65536 + i]);
        num += a * h;
        den += a;
    }
    pn[seg * 65536 + i] = num;
    pd[seg * 65536 + i] = den;
}

__global__ __launch_bounds__(256) void pool_final_kernel(
    const float* __restrict__ pn, const float* __restrict__ pd,
    float* __restrict__ out)
{
    int i = blockIdx.x * 256 + threadIdx.x;
    float num = 0.f, den = 0.f;
#pragma unroll
    for (int s = 0; s < 4; s++) {
        num += pn[s * 65536 + i];
        den += pd[s * 65536 + i];
    }
    out[i] = num / den;
}

// ---------------------------------------------------------------------------
extern "C" void kernel_launch(void* const* d_in, const int* in_sizes, int n_in,
                              void* d_out, int out_size)
{
    const float* x    = (const float*)d_in[0];
    const float* h_w1 = (const float*)d_in[1];
    const float* h_b1 = (const float*)d_in[2];
    const float* h_w2 = (const float*)d_in[3];
    const float* h_b2 = (const float*)d_in[4];
    const float* h_w3 = (const float*)d_in[5];
    const float* h_b3 = (const float*)d_in[6];
    const float* i_w1 = (const float*)d_in[7];
    const float* i_b1 = (const float*)d_in[8];
    const float* i_w2 = (const float*)d_in[9];
    const float* i_b2 = (const float*)d_in[10];
    const float* i_w3 = (const float*)d_in[11];
    const float* i_b3 = (const float*)d_in[12];
    const float* att_w = (const float*)d_in[13];
    const float* att_b = (const float*)d_in[14];
    float* out = (float*)d_out;

    float *buf1, *buf2, *xin, *hs;
    cudaGetSymbolAddress((void**)&buf1, g_buf1);
    cudaGetSymbolAddress((void**)&buf2, g_buf2);
    cudaGetSymbolAddress((void**)&xin,  g_xin);
    cudaGetSymbolAddress((void**)&hs,   g_hs);

    const int M = 131072;
    const int smem_rnn = SMF_TOT * 4;
    cudaFuncSetAttribute(rnn_kernel,
                         cudaFuncAttributeMaxDynamicSharedMemorySize, smem_rnn);
    cudaFuncSetAttribute(gemm_tc<1, 0>,
                         cudaFuncAttributeMaxDynamicSharedMemorySize, GEMM_SMEM);
    cudaFuncSetAttribute(gemm_tc<0, 1>,
                         cudaFuncAttributeMaxDynamicSharedMemorySize, GEMM_SMEM);
    cudaFuncSetAttribute(gemm_tc<2, 0>,
                         cudaFuncAttributeMaxDynamicSharedMemorySize, GEMM_SMEM);

    // Input MLP (tensor cores): x -> relu -> relu -> xin_t (scatter [T][B][H])
    gemm_tc<1, 0><<<(M / 128) * (512 / 64), 256, GEMM_SMEM>>>(x,    i_w1, i_b1, buf1, M, 512, 128);
    gemm_tc<1, 0><<<(M / 128) * (512 / 64), 256, GEMM_SMEM>>>(buf1, i_w2, i_b2, buf2, M, 512, 512);
    gemm_tc<0, 1><<<(M / 128) * (256 / 64), 256, GEMM_SMEM>>>(buf2, i_w3, i_b3, xin,  M, 256, 512);

    // Persistent recurrence (16-CTA flag barrier, self-basing phases)
    rnn_kernel<<<NRNN, 256, smem_rnn>>>(h_w1, h_b1, h_w2, h_b2, h_w3, h_b3);

    // Attention weights: exp(tanh(hs @ att_w + att_b)) -> buf1 (reused)
    gemm_tc<2, 0><<<(M / 128) * (256 / 64), 256, GEMM_SMEM>>>(hs, att_w, att_b, buf1, M, 256, 256);

    // Pool over T, 2-stage (partials in buf2 scratch)
    pool_partial_kernel<<<1024, 256>>>(buf1, hs, buf2, buf2 + 262144);
    pool_final_kernel<<<256, 256>>>(buf2, buf2 + 262144, out);
}

// round 17
// speedup vs baseline: 1.1102x; 1.0309x over previous
#include <cuda_runtime.h>
#include <cstdint>

// Shapes: B=256, T=512, IN=128, H=256, W1=W2=512. M = B*T = 131072.
#define NRNN 128

// ---------------- static device scratch (no allocation allowed) ------------
__device__ float g_buf1[131072u * 512u];   // input-MLP act1; later attn weights
__device__ float g_buf2[131072u * 512u];   // input-MLP act2; later pool partials
__device__ float g_xin [512u * 65536u];    // xin_t  [T][B][H]
__device__ float g_hs  [512u * 65536u];    // hidden states [T][B][H]
__device__ float g_a1  [2 * 256 * 512];    // parity-buffered layer-1 act
__device__ float g_a2  [2 * 256 * 512];    // parity-buffered layer-2 act
__device__ unsigned g_flags[8 * 16 * 32];  // [mg][cta] flags, 128B stride (zero-init)

// ---------------------------------------------------------------------------
// helpers
// ---------------------------------------------------------------------------
__device__ __forceinline__ unsigned f2tf(float f)
{
    unsigned u;
    asm("cvt.rna.tf32.f32 %0, %1;" : "=r"(u) : "f"(f));
    return u;
}

// fast tanh: 1 - 2/(e^{2x}+1); exact limits at +-inf, MUFU-based.
__device__ __forceinline__ float ftanh(float x)
{
    float e = __expf(2.f * x);
    return 1.f - 2.f / (e + 1.f);
}

__device__ __forceinline__ void mma_tf32(
    float& c0, float& c1, float& c2, float& c3,
    unsigned a0, unsigned a1, unsigned a2, unsigned a3,
    unsigned b0, unsigned b1)
{
    asm volatile(
        "mma.sync.aligned.m16n8k8.row.col.f32.tf32.tf32.f32 "
        "{%0,%1,%2,%3},{%4,%5,%6,%7},{%8,%9},{%0,%1,%2,%3};"
        : "+f"(c0), "+f"(c1), "+f"(c2), "+f"(c3)
        : "r"(a0), "r"(a1), "r"(a2), "r"(a3), "r"(b0), "r"(b1));
}

// ---------------------------------------------------------------------------
// Big tf32 tensor-core GEMM: C = act(A@W + bias). Block 128x64, BK=32,
// 256 threads = 8 warps, ping-pong smem tiles, 2 CTAs/SM.
// ACT: 0 none, 1 relu, 2 exp(tanh()). PERM: 0 row-major; 1 (b*T+t)->[t][b][:].
// ---------------------------------------------------------------------------
#define GEMM_SMEM ((2 * 128 * 36 + 2 * 64 * 36) * 4)

template <int ACT, int PERM>
__global__ __launch_bounds__(256, 2) void gemm_tc(
    const float* __restrict__ A, const float* __restrict__ W,
    const float* __restrict__ bias, float* __restrict__ C,
    int M, int N, int K)
{
    extern __shared__ unsigned gsm[];
    unsigned* AsB = gsm;
    unsigned* BsB = gsm + 2 * 128 * 36;

    const int nb  = N >> 6;
    const int bm  = (int)(blockIdx.x / nb) << 7;
    const int bn  = (int)(blockIdx.x % nb) << 6;
    const int tid = threadIdx.x;
    const int w    = tid >> 5;
    const int lane = tid & 31;
    const int g    = lane >> 2;
    const int tg   = lane & 3;
    const int wm   = (w & 3) << 5;
    const int wn   = (w >> 2) << 5;

    const int arow = tid >> 3;
    const int akq  = (tid & 7) << 2;
    const int bk   = tid >> 4;
    const int bnq  = (tid & 15) << 2;

    float acc[2][4][4];
#pragma unroll
    for (int mi = 0; mi < 2; mi++)
#pragma unroll
        for (int ni = 0; ni < 4; ni++)
#pragma unroll
            for (int q = 0; q < 4; q++) acc[mi][ni][q] = 0.f;

    float4 pa[4], pb[2];
#pragma unroll
    for (int i = 0; i < 4; i++)
        pa[i] = *reinterpret_cast<const float4*>(
            A + (size_t)(bm + arow + (i << 5)) * K + akq);
#pragma unroll
    for (int i = 0; i < 2; i++)
        pb[i] = *reinterpret_cast<const float4*>(
            W + (size_t)(bk + (i << 4)) * N + bn + bnq);

    for (int p = 0; p < K; p += 32) {
        const int bsel = (p >> 5) & 1;
        unsigned* As = AsB + bsel * (128 * 36);
        unsigned* Bs = BsB + bsel * (64 * 36);

#pragma unroll
        for (int i = 0; i < 4; i++) {
            uint4 q;
            q.x = f2tf(pa[i].x); q.y = f2tf(pa[i].y);
            q.z = f2tf(pa[i].z); q.w = f2tf(pa[i].w);
            *reinterpret_cast<uint4*>(&As[(arow + (i << 5)) * 36 + akq]) = q;
        }
#pragma unroll
        for (int i = 0; i < 2; i++) {
            int k = bk + (i << 4);
            Bs[(bnq + 0) * 36 + k] = f2tf(pb[i].x);
            Bs[(bnq + 1) * 36 + k] = f2tf(pb[i].y);
            Bs[(bnq + 2) * 36 + k] = f2tf(pb[i].z);
            Bs[(bnq + 3) * 36 + k] = f2tf(pb[i].w);
        }
        __syncthreads();

        if (p + 32 < K) {
#pragma unroll
            for (int i = 0; i < 4; i++)
                pa[i] = *reinterpret_cast<const float4*>(
                    A + (size_t)(bm + arow + (i << 5)) * K + p + 32 + akq);
#pragma unroll
            for (int i = 0; i < 2; i++)
                pb[i] = *reinterpret_cast<const float4*>(
                    W + (size_t)(p + 32 + bk + (i << 4)) * N + bn + bnq);
        }

#pragma unroll
        for (int ks = 0; ks < 4; ks++) {
            int kb = ks << 3;
            unsigned a[2][4];
#pragma unroll
            for (int mi = 0; mi < 2; mi++) {
                const unsigned* ap = &As[(wm + (mi << 4) + g) * 36 + tg + kb];
                a[mi][0] = ap[0];
                a[mi][1] = ap[8 * 36];
                a[mi][2] = ap[4];
                a[mi][3] = ap[8 * 36 + 4];
            }
#pragma unroll
            for (int ni = 0; ni < 4; ni++) {
                const unsigned* bp = &Bs[(wn + (ni << 3) + g) * 36 + tg + kb];
                unsigned b0 = bp[0], b1 = bp[4];
#pragma unroll
                for (int mi = 0; mi < 2; mi++)
                    mma_tf32(acc[mi][ni][0], acc[mi][ni][1],
                             acc[mi][ni][2], acc[mi][ni][3],
                             a[mi][0], a[mi][1], a[mi][2], a[mi][3], b0, b1);
            }
        }
    }

#pragma unroll
    for (int mi = 0; mi < 2; mi++) {
#pragma unroll
        for (int ni = 0; ni < 4; ni++) {
            int col = bn + wn + (ni << 3) + (tg << 1);
            float b0v = __ldg(&bias[col]);
            float b1v = __ldg(&bias[col + 1]);
#pragma unroll
            for (int half = 0; half < 2; half++) {
                int r = bm + wm + (mi << 4) + g + (half << 3);
                float2 vv;
                vv.x = acc[mi][ni][half ? 2 : 0] + b0v;
                vv.y = acc[mi][ni][half ? 3 : 1] + b1v;
                if (ACT == 1) { vv.x = fmaxf(vv.x, 0.f); vv.y = fmaxf(vv.y, 0.f); }
                if (ACT == 2) { vv.x = __expf(ftanh(vv.x)); vv.y = __expf(ftanh(vv.y)); }
                if (PERM == 0) {
                    *reinterpret_cast<float2*>(&C[(size_t)r * N + col]) = vv;
                } else {
                    int b = r >> 9;
                    int t = r & 511;
                    *reinterpret_cast<float2*>(
                        &C[((size_t)t << 16) + (b << 8) + col]) = vv;
                }
            }
        }
    }
}

// ---------------------------------------------------------------------------
// Dataflow sync: per-CTA monotonic release flags; half-width waits polled by
// <=8 lanes of warp 0 only (R13 lesson: never poll from all threads).
// Self-basing phases (zero-init; all group members end a launch equal).
// ---------------------------------------------------------------------------
__device__ __forceinline__ void mg_release(unsigned* myflag, unsigned ph)
{
    __syncthreads();   // all this layer's stores complete before publication
    if (threadIdx.x == 0)
        asm volatile("st.release.gpu.u32 [%0], %1;" :: "l"(myflag), "r"(ph) : "memory");
}

__device__ __forceinline__ void poll_one(const unsigned* p, unsigned target)
{
    unsigned v;
    do {
        asm volatile("ld.acquire.gpu.u32 %0, [%1];" : "=r"(v) : "l"(p) : "memory");
    } while (v < target);
}

// ---------------------------------------------------------------------------
// Recurrent layers. 128 CTAs = 8 Mg(32 rows) x 16 Ns. 256 threads = 8 warps.
// Weights tf32 W^T[n][k] in SMEM; ping-pong As staging; dual accumulator
// chains. Dataflow waits: first half of producers upfront (8-wide), second
// half overlapped with chunk-0 prefetch+mma and sealed by the chunk-1 sync.
// ---------------------------------------------------------------------------
#define PADA 132
#define ABUF (32 * PADA)

// Layer 1: K=256 (2 chunks). Chunk0 producers = CTAs 0-7 (l3 cols 0-127),
// chunk1 producers = CTAs 8-15. relu -> a1 parity buffer.
__device__ __forceinline__ void layer1_mma(
    const float* __restrict__ A,            // hs[t-1], lda=256
    const unsigned* __restrict__ Wt,        // stride 260
    const float* __restrict__ bias_s,
    float* __restrict__ C,                  // a1 parity, ldc=512
    unsigned* As, int bm, int bn,
    const unsigned* fbase, unsigned target)
{
    const int tid  = threadIdx.x;
    const int w    = tid >> 5;
    const int lane = tid & 31;
    const int g    = lane >> 2;
    const int tg   = lane & 3;
    const int r0 = (w & 1) << 4;
    const int n0 = (w >> 1) << 3;
    const int lr = w;
    const int lq = lane << 2;

    if (tid < 8) poll_one(fbase + tid * 32, target);       // producers 0-7
    __syncthreads();

    float4 pf[4];
#pragma unroll
    for (int i = 0; i < 4; i++)
        pf[i] = __ldcg(reinterpret_cast<const float4*>(
            A + (size_t)(bm + lr + i * 8) * 256 + lq));

    // second half overlaps the chunk-0 LDG latency; sealed by staging syncs
    if (tid < 8) poll_one(fbase + (8 + tid) * 32, target); // producers 8-15

    float e0 = 0.f, e1 = 0.f, e2 = 0.f, e3 = 0.f;
    float o0 = 0.f, o1 = 0.f, o2 = 0.f, o3 = 0.f;

#pragma unroll
    for (int c = 0; c < 2; c++) {
        unsigned* buf = As + (c & 1) * ABUF;
#pragma unroll
        for (int i = 0; i < 4; i++) {
            uint4 q;
            q.x = f2tf(pf[i].x); q.y = f2tf(pf[i].y);
            q.z = f2tf(pf[i].z); q.w = f2tf(pf[i].w);
            *reinterpret_cast<uint4*>(buf + (lr + i * 8) * PADA + lq) = q;
        }
        __syncthreads();   // also propagates warp0's second-half confirmation

        if (c == 0) {
            const float* An = A + 128;
#pragma unroll
            for (int i = 0; i < 4; i++)
                pf[i] = __ldcg(reinterpret_cast<const float4*>(
                    An + (size_t)(bm + lr + i * 8) * 256 + lq));
        }

        const unsigned* ap = buf + (r0 + g) * PADA + tg;
        const unsigned* bp = Wt + (size_t)(n0 + g) * 260 + c * 128 + tg;
#pragma unroll
        for (int k8 = 0; k8 < 16; k8 += 2) {
            int kb = k8 << 3;
            mma_tf32(e0, e1, e2, e3,
                     ap[kb], ap[8 * PADA + kb], ap[kb + 4], ap[8 * PADA + kb + 4],
                     bp[kb], bp[kb + 4]);
            int kc = kb + 8;
            mma_tf32(o0, o1, o2, o3,
                     ap[kc], ap[8 * PADA + kc], ap[kc + 4], ap[8 * PADA + kc + 4],
                     bp[kc], bp[kc + 4]);
        }
    }

    int row0 = bm + r0 + g;
    int col  = bn + n0 + (tg << 1);
    float b0v = bias_s[n0 + (tg << 1)];
    float b1v = bias_s[n0 + (tg << 1) + 1];
    float2 v0, v1;
    v0.x = fmaxf(e0 + o0 + b0v, 0.f); v0.y = fmaxf(e1 + o1 + b1v, 0.f);
    v1.x = fmaxf(e2 + o2 + b0v, 0.f); v1.y = fmaxf(e3 + o3 + b1v, 0.f);
    __stcg(reinterpret_cast<float2*>(&C[(size_t)row0 * 512 + col]), v0);
    __stcg(reinterpret_cast<float2*>(&C[(size_t)(row0 + 8) * 512 + col]), v1);
}

// Layer 2: K=512 (4 chunks). Chunk c producers = CTAs 4c..4c+3. Upfront wait
// covers chunks 0-1 (producers 0-7); producers 8-15 polled by warp0 during
// chunk-0 mma, sealed by the chunk-1 staging sync. relu -> a2 parity buffer.
__device__ __forceinline__ void layer2_mma(
    const float* __restrict__ A,            // a1 parity, lda=512
    const unsigned* __restrict__ Wt,        // stride 516
    const float* __restrict__ bias_s,
    float* __restrict__ C,                  // a2 parity, ldc=512
    unsigned* As, int bm, int bn,
    const unsigned* fbase, unsigned target)
{
    const int tid  = threadIdx.x;
    const int w    = tid >> 5;
    const int lane = tid & 31;
    const int g    = lane >> 2;
    const int tg   = lane & 3;
    const int r0 = (w & 1) << 4;
    const int n0 = (w >> 1) << 3;
    const int lr = w;
    const int lq = lane << 2;

    if (tid < 8) poll_one(fbase + tid * 32, target);       // producers 0-7
    __syncthreads();

    float4 pf[4];
#pragma unroll
    for (int i = 0; i < 4; i++)
        pf[i] = __ldcg(reinterpret_cast<const float4*>(
            A + (size_t)(bm + lr + i * 8) * 512 + lq));

    float e0 = 0.f, e1 = 0.f, e2 = 0.f, e3 = 0.f;
    float o0 = 0.f, o1 = 0.f, o2 = 0.f, o3 = 0.f;

#pragma unroll
    for (int c = 0; c < 4; c++) {
        unsigned* buf = As + (c & 1) * ABUF;
#pragma unroll
        for (int i = 0; i < 4; i++) {
            uint4 q;
            q.x = f2tf(pf[i].x); q.y = f2tf(pf[i].y);
            q.z = f2tf(pf[i].z); q.w = f2tf(pf[i].w);
            *reinterpret_cast<uint4*>(buf + (lr + i * 8) * PADA + lq) = q;
        }
        __syncthreads();   // chunk-1's instance propagates the 8-15 wait

        if (c + 1 < 4) {   // chunk1 producers confirmed upfront; chunk2/3 by poll
            const float* An = A + (c + 1) * 128;
#pragma unroll
            for (int i = 0; i < 4; i++)
                pf[i] = __ldcg(reinterpret_cast<const float4*>(
                    An + (size_t)(bm + lr + i * 8) * 512 + lq));
        }
        if (c == 0 && tid < 8)
            poll_one(fbase + (8 + tid) * 32, target);      // producers 8-15

        const unsigned* ap = buf + (r0 + g) * PADA + tg;
        const unsigned* bp = Wt + (size_t)(n0 + g) * 516 + c * 128 + tg;
#pragma unroll
        for (int k8 = 0; k8 < 16; k8 += 2) {
            int kb = k8 << 3;
            mma_tf32(e0, e1, e2, e3,
                     ap[kb], ap[8 * PADA + kb], ap[kb + 4], ap[8 * PADA + kb + 4],
                     bp[kb], bp[kb + 4]);
            int kc = kb + 8;
            mma_tf32(o0, o1, o2, o3,
                     ap[kc], ap[8 * PADA + kc], ap[kc + 4], ap[8 * PADA + kc + 4],
                     bp[kc], bp[kc + 4]);
        }
    }

    int row0 = bm + r0 + g;
    int col  = bn + n0 + (tg << 1);
    float b0v = bias_s[n0 + (tg << 1)];
    float b1v = bias_s[n0 + (tg << 1) + 1];
    float2 v0, v1;
    v0.x = fmaxf(e0 + o0 + b0v, 0.f); v0.y = fmaxf(e1 + o1 + b1v, 0.f);
    v1.x = fmaxf(e2 + o2 + b0v, 0.f); v1.y = fmaxf(e3 + o3 + b1v, 0.f);
    __stcg(reinterpret_cast<float2*>(&C[(size_t)row0 * 512 + col]), v0);
    __stcg(reinterpret_cast<float2*>(&C[(size_t)(row0 + 8) * 512 + col]), v1);
}

// Layer 3: K=512, parallel split-K. Warp-group g2 owns chunks {2g2, 2g2+1}
// (producers 8g2..8g2+7, waited per-group, 8-wide). Per-group As buffers +
// named barriers; xchg merge; tanh(v+xin) -> hs[t].
__device__ __forceinline__ void layer3_mma(
    const float* __restrict__ A,            // a2 parity, lda=512
    const unsigned* __restrict__ Wt,        // stride 516
    const float* __restrict__ bias_s,
    float* __restrict__ C,                  // hs[t], ldc=256
    const float* __restrict__ xin,
    unsigned* As4, float* xchg, int bm, int bn,
    const unsigned* fbase, unsigned target)
{
    const int tid  = threadIdx.x;
    const int w    = tid >> 5;
    const int lane = tid & 31;
    const int g    = lane >> 2;
    const int tg   = lane & 3;
    const int g2   = w >> 2;
    const int w2   = w & 3;
    const int r0   = (w2 & 1) << 4;
    const int n0   = ((w2 >> 1) & 1) << 3;
    const int ltid = tid & 127;
    const int lr   = ltid >> 5;
    const int lq   = (ltid & 31) << 2;
    const int barid = 1 + g2;

    if (w2 == 0 && lane < 8)
        poll_one(fbase + (g2 * 8 + lane) * 32, target);
    asm volatile("bar.sync %0, 128;" :: "r"(barid));

    const float* A0 = A + (size_t)g2 * 256;
    float4 pf[8];
#pragma unroll
    for (int i = 0; i < 8; i++)
        pf[i] = __ldcg(reinterpret_cast<const float4*>(
            A0 + (size_t)(bm + lr + i * 4) * 512 + lq));

    float e0 = 0.f, e1 = 0.f, e2 = 0.f, e3 = 0.f;
    float o0 = 0.f, o1 = 0.f, o2 = 0.f, o3 = 0.f;

#pragma unroll
    for (int cc = 0; cc < 2; cc++) {
        int c = (g2 << 1) + cc;
        unsigned* buf = As4 + ((g2 << 1) + cc) * ABUF;
#pragma unroll
        for (int i = 0; i < 8; i++) {
            uint4 q;
            q.x = f2tf(pf[i].x); q.y = f2tf(pf[i].y);
            q.z = f2tf(pf[i].z); q.w = f2tf(pf[i].w);
            *reinterpret_cast<uint4*>(buf + (lr + i * 4) * PADA + lq) = q;
        }
        asm volatile("bar.sync %0, 128;" :: "r"(barid));

        if (cc == 0) {
            const float* A1 = A0 + 128;
#pragma unroll
            for (int i = 0; i < 8; i++)
                pf[i] = __ldcg(reinterpret_cast<const float4*>(
                    A1 + (size_t)(bm + lr + i * 4) * 512 + lq));
        }

        const unsigned* ap = buf + (r0 + g) * PADA + tg;
        const unsigned* bp = Wt + (size_t)(n0 + g) * 516 + c * 128 + tg;
#pragma unroll
        for (int k8 = 0; k8 < 16; k8 += 2) {
            int kb = k8 << 3;
            mma_tf32(e0, e1, e2, e3,
                     ap[kb], ap[8 * PADA + kb], ap[kb + 4], ap[8 * PADA + kb + 4],
                     bp[kb], bp[kb + 4]);
            int kc = kb + 8;
            mma_tf32(o0, o1, o2, o3,
                     ap[kc], ap[8 * PADA + kc], ap[kc + 4], ap[8 * PADA + kc + 4],
                     bp[kc], bp[kc + 4]);
        }
    }

    float c0 = e0 + o0, c1 = e1 + o1, c2 = e2 + o2, c3 = e3 + o3;
    float* xb = xchg + w2 * 128 + lane * 4;
    if (g2 == 1) { xb[0] = c0; xb[1] = c1; xb[2] = c2; xb[3] = c3; }
    __syncthreads();
    if (g2 == 0) {
        c0 += xb[0]; c1 += xb[1]; c2 += xb[2]; c3 += xb[3];
        int row0 = bm + r0 + g;
        int col  = bn + n0 + (tg << 1);
        float b0v = bias_s[n0 + (tg << 1)];
        float b1v = bias_s[n0 + (tg << 1) + 1];
        float2 x0 = *reinterpret_cast<const float2*>(&xin[(size_t)row0 * 256 + col]);
        float2 x1 = *reinterpret_cast<const float2*>(&xin[(size_t)(row0 + 8) * 256 + col]);
        float2 v0, v1;
        v0.x = ftanh(c0 + b0v + x0.x); v0.y = ftanh(c1 + b1v + x0.y);
        v1.x = ftanh(c2 + b0v + x1.x); v1.y = ftanh(c3 + b1v + x1.y);
        __stcg(reinterpret_cast<float2*>(&C[(size_t)row0 * 256 + col]), v0);
        __stcg(reinterpret_cast<float2*>(&C[(size_t)(row0 + 8) * 256 + col]), v1);
    }
}

// SMEM (4B words): Wt1 32x260 | Wt2 32x516 | Wt3 16x516 | bias 80 | As 4x32x132 | xchg 512
#define SMF_WT1  0
#define SMF_WT2  8320
#define SMF_WT3  (8320 + 16512)
#define SMF_B    (SMF_WT3 + 8256)
#define SMF_AS   (SMF_B + 80)
#define SMF_XCHG (SMF_AS + 4 * ABUF)
#define SMF_TOT  (SMF_XCHG + 512)

__global__ __launch_bounds__(256, 1) void rnn_kernel(
    const float* __restrict__ W1, const float* __restrict__ b1,
    const float* __restrict__ W2, const float* __restrict__ b2,
    const float* __restrict__ W3, const float* __restrict__ b3)
{
    extern __shared__ unsigned smu[];
    unsigned* Wt1 = smu + SMF_WT1;
    unsigned* Wt2 = smu + SMF_WT2;
    unsigned* Wt3 = smu + SMF_WT3;
    float*    bs  = reinterpret_cast<float*>(smu + SMF_B);
    unsigned* As  = smu + SMF_AS;
    float*   xchg = reinterpret_cast<float*>(smu + SMF_XCHG);
    __shared__ unsigned s_base;

    const int tid = threadIdx.x;
    const int mg  = blockIdx.x >> 4;      // 0..7
    const int ns  = blockIdx.x & 15;      // 0..15
    const int bm  = mg << 5;              // 32-row group
    const int bn  = ns << 5;              // 32-col slice (l1,l2)
    const int bn3 = ns << 4;              // 16-col slice (l3)

    const unsigned* fbase = &g_flags[(mg * 16) * 32];
    unsigned* myflag = &g_flags[(mg * 16 + ns) * 32];

    // self-basing phase: read my own flag (group members end a launch equal)
    if (tid == 0) {
        unsigned v;
        asm volatile("ld.acquire.gpu.u32 %0, [%1];"
                     : "=r"(v) : "l"(myflag) : "memory");
        s_base = v;
    }

    // one-time tf32 weight slice load: W^T[n][k]
    for (int idx = tid; idx < 8192; idx += 256) {       // Wt1 [32][256] str 260
        int c = idx >> 8, k = idx & 255;
        Wt1[c * 260 + k] = f2tf(__ldg(&W1[k * 512 + bn + c]));
    }
    for (int idx = tid; idx < 16384; idx += 256) {      // Wt2 [32][512] str 516
        int c = idx >> 9, k = idx & 511;
        Wt2[c * 516 + k] = f2tf(__ldg(&W2[k * 512 + bn + c]));
    }
    for (int idx = tid; idx < 8192; idx += 256) {       // Wt3 [16][512] str 516
        int c = idx >> 9, k = idx & 511;
        Wt3[c * 516 + k] = f2tf(__ldg(&W3[k * 256 + bn3 + c]));
    }
    if (tid < 32)      bs[tid]      = __ldg(&b1[bn + tid]);
    else if (tid < 64) bs[tid]      = __ldg(&b2[bn + tid - 32]);
    else if (tid < 80) bs[tid]      = __ldg(&b3[bn3 + tid - 64]);
    __syncthreads();

    const unsigned base = s_base;

    // t = 0: h_{-1} = 0  =>  a1[parity0] = relu(b1); release acts as l1(0)
    {
        int r  = tid >> 3;
        int cb = (tid & 7) << 2;
        float4 v;
        v.x = fmaxf(bs[cb], 0.f);     v.y = fmaxf(bs[cb + 1], 0.f);
        v.z = fmaxf(bs[cb + 2], 0.f); v.w = fmaxf(bs[cb + 3], 0.f);
        __stcg(reinterpret_cast<float4*>(&g_a1[(size_t)(bm + r) * 512 + bn + cb]), v);
    }
    mg_release(myflag, base + 1);

    for (int t = 0; t < 512; t++) {
        float* a1b = g_a1 + (size_t)(t & 1) * 131072u;
        float* a2b = g_a2 + (size_t)(t & 1) * 131072u;
        const unsigned tgt = base + 3u * (unsigned)t;
        if (t > 0) {
            layer1_mma(g_hs + (size_t)(t - 1) * 65536, Wt1, bs,
                       a1b, As, bm, bn, fbase, tgt);
            mg_release(myflag, tgt + 1);
        }
        layer2_mma(a1b, Wt2, bs + 32, a2b, As, bm, bn, fbase, tgt + 1);
        mg_release(myflag, tgt + 2);
        layer3_mma(a2b, Wt3, bs + 64,
                   g_hs + (size_t)t * 65536,
                   g_xin + (size_t)t * 65536, As, xchg, bm, bn3, fbase, tgt + 2);
        mg_release(myflag, tgt + 3);
    }
}

// ---------------------------------------------------------------------------
// Attention pool, 2-stage: partials over T/4 segments, then reduce + divide.
// ---------------------------------------------------------------------------
__global__ __launch_bounds__(256) void pool_partial_kernel(
    const float* __restrict__ aw, const float* __restrict__ hs,
    float* __restrict__ pn, float* __restrict__ pd)
{
    int seg = blockIdx.x >> 8;
    int i   = (blockIdx.x & 255) * 256 + threadIdx.x;
    float num = 0.f, den = 0.f;
    int t0 = seg * 128;
#pragma unroll 4
    for (int t = t0; t < t0 + 128; t++) {
        float a = __ldg(&aw[(size_t)t * 65536 + i]);
        float h = __ldg(&hs[(size_t)t * 65536 + i]);
        num += a * h;
        den += a;
    }
    pn[seg * 65536 + i] = num;
    pd[seg * 65536 + i] = den;
}

__global__ __launch_bounds__(256) void pool_final_kernel(
    const float* __restrict__ pn, const float* __restrict__ pd,
    float* __restrict__ out)
{
    int i = blockIdx.x * 256 + threadIdx.x;
    float num = 0.f, den = 0.f;
#pragma unroll
    for (int s = 0; s < 4; s++) {
        num += pn[s * 65536 + i];
        den += pd[s * 65536 + i];
    }
    out[i] = num / den;
}

// ---------------------------------------------------------------------------
extern "C" void kernel_launch(void* const* d_in, const int* in_sizes, int n_in,
                              void* d_out, int out_size)
{
    const float* x    = (const float*)d_in[0];
    const float* h_w1 = (const float*)d_in[1];
    const float* h_b1 = (const float*)d_in[2];
    const float* h_w2 = (const float*)d_in[3];
    const float* h_b2 = (const float*)d_in[4];
    const float* h_w3 = (const float*)d_in[5];
    const float* h_b3 = (const float*)d_in[6];
    const float* i_w1 = (const float*)d_in[7];
    const float* i_b1 = (const float*)d_in[8];
    const float* i_w2 = (const float*)d_in[9];
    const float* i_b2 = (const float*)d_in[10];
    const float* i_w3 = (const float*)d_in[11];
    const float* i_b3 = (const float*)d_in[12];
    const float* att_w = (const float*)d_in[13];
    const float* att_b = (const float*)d_in[14];
    float* out = (float*)d_out;

    float *buf1, *buf2, *xin, *hs;
    cudaGetSymbolAddress((void**)&buf1, g_buf1);
    cudaGetSymbolAddress((void**)&buf2, g_buf2);
    cudaGetSymbolAddress((void**)&xin,  g_xin);
    cudaGetSymbolAddress((void**)&hs,   g_hs);

    const int M = 131072;
    const int smem_rnn = SMF_TOT * 4;
    cudaFuncSetAttribute(rnn_kernel,
                         cudaFuncAttributeMaxDynamicSharedMemorySize, smem_rnn);
    cudaFuncSetAttribute(gemm_tc<1, 0>,
                         cudaFuncAttributeMaxDynamicSharedMemorySize, GEMM_SMEM);
    cudaFuncSetAttribute(gemm_tc<0, 1>,
                         cudaFuncAttributeMaxDynamicSharedMemorySize, GEMM_SMEM);
    cudaFuncSetAttribute(gemm_tc<2, 0>,
                         cudaFuncAttributeMaxDynamicSharedMemorySize, GEMM_SMEM);

    // Input MLP (tensor cores): x -> relu -> relu -> xin_t (scatter [T][B][H])
    gemm_tc<1, 0><<<(M / 128) * (512 / 64), 256, GEMM_SMEM>>>(x,    i_w1, i_b1, buf1, M, 512, 128);
    gemm_tc<1, 0><<<(M / 128) * (512 / 64), 256, GEMM_SMEM>>>(buf1, i_w2, i_b2, buf2, M, 512, 512);
    gemm_tc<0, 1><<<(M / 128) * (256 / 64), 256, GEMM_SMEM>>>(buf2, i_w3, i_b3, xin,  M, 256, 512);

    // Persistent recurrence: dataflow flags, half-width single-warp waits
    rnn_kernel<<<NRNN, 256, smem_rnn>>>(h_w1, h_b1, h_w2, h_b2, h_w3, h_b3);

    // Attention weights: exp(tanh(hs @ att_w + att_b)) -> buf1 (reused)
    gemm_tc<2, 0><<<(M / 128) * (256 / 64), 256, GEMM_SMEM>>>(hs, att_w, att_b, buf1, M, 256, 256);

    // Pool over T, 2-stage (partials in buf2 scratch)
    pool_partial_kernel<<<1024, 256>>>(buf1, hs, buf2, buf2 + 262144);
    pool_final_kernel<<<256, 256>>>(buf2, buf2 + 262144, out);
}